// round 7
// baseline (speedup 1.0000x reference)
#include <cuda_runtime.h>
#include <cstdint>

#define D_MODEL 2048
#define BATCH   16384
#define MT 128
#define NT 64
#define A_STAGE 16384
#define STAGE_BYTES 29696        // A 16KB + B 13.3KB
#define SM_DEC (3*STAGE_BYTES)   // 89088
#define SMEM_TOTAL (SM_DEC + 512)

// scratch: x in A-fragment order, weights in B-fragment order
__device__ float g_xA[33554432];   // [rt 0..1023][t 0..255][128 w]
__device__ float g_WB[6815744];    // [cb 0..31][bt 0..12][t 0..255][64 w]

__device__ __forceinline__ float tf32r(float x) {
    float y; asm("cvt.rna.tf32.f32 %0, %1;" : "=f"(y) : "f"(x)); return y;
}
__device__ __forceinline__ uint32_t smem_u32(const void* p) {
    uint32_t a;
    asm("{ .reg .u64 t; cvta.to.shared.u64 t, %1; cvt.u32.u64 %0, t; }" : "=r"(a) : "l"(p));
    return a;
}
__device__ __forceinline__ void cp16(uint32_t dst, const void* src) {
    asm volatile("cp.async.cg.shared.global [%0], [%1], 16;" :: "r"(dst), "l"(src));
}
__device__ __forceinline__ void lds128(uint32_t* r, uint32_t a) {
    asm volatile("ld.shared.v4.b32 {%0,%1,%2,%3}, [%4];"
                 : "=r"(r[0]), "=r"(r[1]), "=r"(r[2]), "=r"(r[3]) : "r"(a));
}
__device__ __forceinline__ void lds64(uint32_t* r, uint32_t a) {
    asm volatile("ld.shared.v2.b32 {%0,%1}, [%2];" : "=r"(r[0]), "=r"(r[1]) : "r"(a));
}
__device__ __forceinline__ void mma_tf32(float* c, const uint32_t* a, const uint32_t* b) {
    asm volatile(
        "mma.sync.aligned.m16n8k8.row.col.f32.tf32.tf32.f32 "
        "{%0,%1,%2,%3}, {%4,%5,%6,%7}, {%8,%9}, {%0,%1,%2,%3};\n"
        : "+f"(c[0]), "+f"(c[1]), "+f"(c[2]), "+f"(c[3])
        : "r"(a[0]), "r"(a[1]), "r"(a[2]), "r"(a[3]), "r"(b[0]), "r"(b[1]));
}

// ---- preround x: coalesced LDG -> smem permute -> coalesced STG ----
__global__ __launch_bounds__(256) void preround_x(const float* __restrict__ x) {
    __shared__ float sm[16 * 516];
    const int tid = threadIdx.x;
    const int rt = blockIdx.x >> 2, tb = blockIdx.x & 3;
    const float* src = x + (size_t)rt * 16 * D_MODEL + tb * 512;
    #pragma unroll
    for (int i = 0; i < 8; i++) {
        int f4 = tid + i * 256;
        int row = f4 >> 7, c4 = f4 & 127;
        float4 v = *(const float4*)(src + (size_t)row * D_MODEL + c4 * 4);
        v.x = tf32r(v.x); v.y = tf32r(v.y); v.z = tf32r(v.z); v.w = tf32r(v.w);
        *(float4*)&sm[row * 516 + c4 * 4] = v;
    }
    __syncthreads();
    char* dst = (char*)g_xA + (size_t)rt * 131072 + (size_t)tb * 64 * 512;
    #pragma unroll
    for (int i = 0; i < 8; i++) {
        int f4 = tid + i * 256;
        int tl = f4 >> 5, lane = f4 & 31;
        int g = lane >> 2, tg = lane & 3;
        float4 v;
        v.x = sm[ g      * 516 + tl * 8 + tg    ];
        v.y = sm[(g + 8) * 516 + tl * 8 + tg    ];
        v.z = sm[ g      * 516 + tl * 8 + tg + 4];
        v.w = sm[(g + 8) * 516 + tl * 8 + tg + 4];
        *(float4*)(dst + (size_t)tl * 512 + lane * 16) = v;
    }
}

// ---- preround W: W_in/W_angle/W_decay -> concatenated B-fragment order ----
__global__ void preround_w(const float* __restrict__ Wi, const float* __restrict__ Wa,
                           const float* __restrict__ Wd) {
    size_t f = (size_t)blockIdx.x * 256 + threadIdx.x;      // 6815744 total
    int cb = (int)(f / 212992); int rem = (int)(f % 212992);
    int bt = rem >> 14; int rem2 = rem & 16383;
    int t = rem2 >> 6; int w = rem2 & 63;
    int lane = w >> 1, j = w & 1, g = lane >> 2, tg = lane & 3;
    int k = t * 8 + tg + 4 * j;
    float v;
    if (bt < 8)       v = Wi[(size_t)(cb * 64 + bt * 8 + g) * D_MODEL + k];
    else if (bt < 12) v = Wa[(size_t)(cb * 32 + (bt - 8) * 8 + g) * D_MODEL + k];
    else              v = (g == 0) ? Wd[k] : 0.f;
    g_WB[f] = tf32r(v);
}

// ---- main fused kernel: 128 threads, 4 warps (2x2), 3-stage cp.async ----
__global__ void __launch_bounds__(128, 2) givens_main(
    const float* __restrict__ h_prev, const float* __restrict__ b_angle,
    const float* __restrict__ b_decay, const float* __restrict__ b_in,
    float* __restrict__ out)
{
    extern __shared__ __align__(1024) char smem[];
    const uint32_t sb = smem_u32(smem);
    const int tid = threadIdx.x, warp = tid >> 5, lane = tid & 31;
    const int g = lane >> 2, tg = lane & 3;
    const int wm = warp >> 1, wn = warp & 1;            // 2x2 warp grid
    const int by = blockIdx.y, cb = blockIdx.x;
    const int m0 = by * MT, n0 = cb * NT, a0 = n0 >> 1;

    // per-thread cp.async source bases (bytes)
    const char* xA = (const char*)g_xA;
    const char* WB = (const char*)g_WB;
    const size_t axbase = (size_t)by * 1048576 + (size_t)warp * 512 + lane * 16;
    const size_t wbbase = (size_t)cb * 851968 + (size_t)(tid >> 6) * 65536
                        + ((tid >> 4) & 3) * 256 + (tid & 15) * 16;
    const bool btail = (tid < 64);

    float ci[4][4][4] = {};   // mi, nb, frag
    float ca[4][2][4] = {};   // mi, na, frag
    float cd[2][4]    = {};   // 2 mi per warp (wn selects which pair), frag

    #define ISSUE(CHUNK, STG) do {                                              \
        uint32_t sd = sb + (STG) * STAGE_BYTES;                                 \
        _Pragma("unroll")                                                       \
        for (int it = 0; it < 8; it++)                                          \
            cp16(sd + tid * 16 + it * 2048, xA + axbase + (size_t)(CHUNK) * 2048 + (size_t)it * 131072); \
        _Pragma("unroll")                                                       \
        for (int ib = 0; ib < 7; ib++)                                          \
            if (ib < 6 || btail)                                                \
                cp16(sd + 16384 + ib * 2048 + tid * 16, WB + wbbase + (size_t)(CHUNK) * 1024 + (size_t)ib * 131072); \
        asm volatile("cp.async.commit_group;" ::: "memory");                    \
    } while (0)

    ISSUE(0, 0);
    ISSUE(1, 1);

    #pragma unroll 1
    for (int c = 0; c < 64; c++) {
        asm volatile("cp.async.wait_group 1;" ::: "memory");
        __syncthreads();
        if (c + 2 < 64) { ISSUE(c + 2, (c + 2) % 3); }
        else            { asm volatile("cp.async.commit_group;" ::: "memory"); }

        const uint32_t sa = sb + (c % 3) * STAGE_BYTES;
        #pragma unroll
        for (int kt = 0; kt < 4; kt++) {
            uint32_t a[4][4];
            #pragma unroll
            for (int mi = 0; mi < 4; mi++)
                lds128(a[mi], sa + (uint32_t)(((wm * 4 + mi) * 4 + kt) * 512) + lane * 16);
            #pragma unroll
            for (int nb = 0; nb < 4; nb++) {
                uint32_t b[2];
                lds64(b, sa + A_STAGE + (uint32_t)(((wn * 4 + nb) * 4 + kt) * 256) + lane * 8);
                #pragma unroll
                for (int mi = 0; mi < 4; mi++) mma_tf32(ci[mi][nb], a[mi], b);
            }
            #pragma unroll
            for (int na = 0; na < 2; na++) {
                uint32_t b[2];
                lds64(b, sa + A_STAGE + (uint32_t)(((8 + wn * 2 + na) * 4 + kt) * 256) + lane * 8);
                #pragma unroll
                for (int mi = 0; mi < 4; mi++) mma_tf32(ca[mi][na], a[mi], b);
            }
            {   // decay: wn==0 handles mi 0-1, wn==1 handles mi 2-3 (balanced)
                uint32_t b[2];
                lds64(b, sa + A_STAGE + (uint32_t)((12 * 4 + kt) * 256) + lane * 8);
                mma_tf32(cd[0], a[wn * 2 + 0], b);
                mma_tf32(cd[1], a[wn * 2 + 1], b);
            }
        }
    }
    __syncthreads();

    // ---- epilogue ----
    float* ang_sm = (float*)smem;                       // 128 x 33 (stage0 reuse)
    float* dec_sm = (float*)(smem + SM_DEC);            // 128 floats
    const float bdec = b_decay[0];
    if (tg == 0) {
        #pragma unroll
        for (int d2 = 0; d2 < 2; d2++) {
            int mi = wn * 2 + d2;
            int r = wm * 64 + mi * 16 + g;
            dec_sm[r]     = 1.f / (1.f + __expf(-(cd[d2][0] + bdec)));
            dec_sm[r + 8] = 1.f / (1.f + __expf(-(cd[d2][2] + bdec)));
        }
    }
    #pragma unroll
    for (int mi = 0; mi < 4; mi++)
    #pragma unroll
    for (int na = 0; na < 2; na++) {
        int rm  = wm * 64 + mi * 16 + g;
        int cbp = wn * 16 + na * 8 + 2 * tg;
        float bA0 = b_angle[a0 + cbp], bA1 = b_angle[a0 + cbp + 1];
        ang_sm[ rm      * 33 + cbp    ] = ca[mi][na][0] + bA0;
        ang_sm[ rm      * 33 + cbp + 1] = ca[mi][na][1] + bA1;
        ang_sm[(rm + 8) * 33 + cbp    ] = ca[mi][na][2] + bA0;
        ang_sm[(rm + 8) * 33 + cbp + 1] = ca[mi][na][3] + bA1;
    }
    __syncthreads();

    #pragma unroll
    for (int mi = 0; mi < 4; mi++)
    #pragma unroll
    for (int nb = 0; nb < 4; nb++) {
        int cloc = wn * 32 + nb * 8 + 2 * tg;
        float2 bi2 = *(const float2*)&b_in[n0 + cloc];
        #pragma unroll
        for (int h = 0; h < 2; h++) {
            int rloc = wm * 64 + mi * 16 + g + h * 8;
            size_t goff = (size_t)(m0 + rloc) * D_MODEL + n0 + cloc;
            float theta = ang_sm[rloc * 33 + (cloc >> 1)];
            float sn, cs;
            __sincosf(theta, &sn, &cs);
            float2 hp = *(const float2*)&h_prev[goff];
            float d = dec_sm[rloc];
            float2 o;
            o.x = d * (cs * hp.x - sn * hp.y) + ci[mi][nb][h * 2 + 0] + bi2.x;
            o.y = d * (sn * hp.x + cs * hp.y) + ci[mi][nb][h * 2 + 1] + bi2.y;
            *(float2*)&out[goff] = o;
        }
    }
    #undef ISSUE
}

extern "C" void kernel_launch(void* const* d_in, const int* in_sizes, int n_in,
                              void* d_out, int out_size) {
    const float* x       = (const float*)d_in[0];
    const float* h_prev  = (const float*)d_in[1];
    const float* W_angle = (const float*)d_in[2];
    const float* b_angle = (const float*)d_in[3];
    const float* W_decay = (const float*)d_in[4];
    const float* b_decay = (const float*)d_in[5];
    const float* W_in    = (const float*)d_in[6];
    const float* b_in    = (const float*)d_in[7];

    preround_x<<<4096, 256>>>(x);
    preround_w<<<26624, 256>>>(W_in, W_angle, W_decay);

    cudaFuncSetAttribute(givens_main, cudaFuncAttributeMaxDynamicSharedMemorySize, SMEM_TOTAL);
    dim3 grid(D_MODEL / NT, BATCH / MT);
    givens_main<<<grid, 128, SMEM_TOTAL>>>(h_prev, b_angle, b_decay, b_in, (float*)d_out);
}

// round 8
// speedup vs baseline: 1.4109x; 1.4109x over previous
#include <cuda_runtime.h>
#include <cstdint>

#define D_MODEL 2048
#define BATCH   16384
#define MT 128
#define NT 64
#define A_STAGE 16384
#define STAGE_BYTES 29696        // A 16KB + B 13.3KB
#define SM_DEC (3*STAGE_BYTES)   // 89088
#define SMEM_TOTAL (SM_DEC + 512)

// scratch: x in A-fragment order, weights in B-fragment order
__device__ float g_xA[33554432];   // [rt 0..1023][t 0..255][128 w]
__device__ float g_WB[6815744];    // [cb 0..31][bt 0..12][t 0..255][64 w]

__device__ __forceinline__ float tf32r(float x) {
    float y; asm("cvt.rna.tf32.f32 %0, %1;" : "=f"(y) : "f"(x)); return y;
}
__device__ __forceinline__ uint32_t smem_u32(const void* p) {
    uint32_t a;
    asm("{ .reg .u64 t; cvta.to.shared.u64 t, %1; cvt.u32.u64 %0, t; }" : "=r"(a) : "l"(p));
    return a;
}
__device__ __forceinline__ void cp16(uint32_t dst, const void* src) {
    asm volatile("cp.async.cg.shared.global [%0], [%1], 16;" :: "r"(dst), "l"(src));
}
__device__ __forceinline__ void lds128(uint32_t* r, uint32_t a) {
    asm volatile("ld.shared.v4.b32 {%0,%1,%2,%3}, [%4];"
                 : "=r"(r[0]), "=r"(r[1]), "=r"(r[2]), "=r"(r[3]) : "r"(a));
}
__device__ __forceinline__ void lds64(uint32_t* r, uint32_t a) {
    asm volatile("ld.shared.v2.b32 {%0,%1}, [%2];" : "=r"(r[0]), "=r"(r[1]) : "r"(a));
}
__device__ __forceinline__ void mma_tf32(float* c, const uint32_t* a, const uint32_t* b) {
    asm volatile(
        "mma.sync.aligned.m16n8k8.row.col.f32.tf32.tf32.f32 "
        "{%0,%1,%2,%3}, {%4,%5,%6,%7}, {%8,%9}, {%0,%1,%2,%3};\n"
        : "+f"(c[0]), "+f"(c[1]), "+f"(c[2]), "+f"(c[3])
        : "r"(a[0]), "r"(a[1]), "r"(a[2]), "r"(a[3]), "r"(b[0]), "r"(b[1]));
}

// ---- preround x: coalesced LDG -> smem permute -> coalesced STG (42us) ----
__global__ __launch_bounds__(256) void preround_x(const float* __restrict__ x) {
    __shared__ float sm[16 * 516];
    const int tid = threadIdx.x;
    const int rt = blockIdx.x >> 2, tb = blockIdx.x & 3;
    const float* src = x + (size_t)rt * 16 * D_MODEL + tb * 512;
    #pragma unroll
    for (int i = 0; i < 8; i++) {
        int f4 = tid + i * 256;
        int row = f4 >> 7, c4 = f4 & 127;
        float4 v = *(const float4*)(src + (size_t)row * D_MODEL + c4 * 4);
        v.x = tf32r(v.x); v.y = tf32r(v.y); v.z = tf32r(v.z); v.w = tf32r(v.w);
        *(float4*)&sm[row * 516 + c4 * 4] = v;
    }
    __syncthreads();
    char* dst = (char*)g_xA + (size_t)rt * 131072 + (size_t)tb * 64 * 512;
    #pragma unroll
    for (int i = 0; i < 8; i++) {
        int f4 = tid + i * 256;
        int tl = f4 >> 5, lane = f4 & 31;
        int g = lane >> 2, tg = lane & 3;
        float4 v;
        v.x = sm[ g      * 516 + tl * 8 + tg    ];
        v.y = sm[(g + 8) * 516 + tl * 8 + tg    ];
        v.z = sm[ g      * 516 + tl * 8 + tg + 4];
        v.w = sm[(g + 8) * 516 + tl * 8 + tg + 4];
        *(float4*)(dst + (size_t)tl * 512 + lane * 16) = v;
    }
}

// ---- preround W: W_in/W_angle/W_decay -> concatenated B-fragment order ----
__global__ void preround_w(const float* __restrict__ Wi, const float* __restrict__ Wa,
                           const float* __restrict__ Wd) {
    size_t f = (size_t)blockIdx.x * 256 + threadIdx.x;      // 6815744 total
    int cb = (int)(f / 212992); int rem = (int)(f % 212992);
    int bt = rem >> 14; int rem2 = rem & 16383;
    int t = rem2 >> 6; int w = rem2 & 63;
    int lane = w >> 1, j = w & 1, g = lane >> 2, tg = lane & 3;
    int k = t * 8 + tg + 4 * j;
    float v;
    if (bt < 8)       v = Wi[(size_t)(cb * 64 + bt * 8 + g) * D_MODEL + k];
    else if (bt < 12) v = Wa[(size_t)(cb * 32 + (bt - 8) * 8 + g) * D_MODEL + k];
    else              v = (g == 0) ? Wd[k] : 0.f;
    g_WB[f] = tf32r(v);
}

// ---- main fused kernel: R3 mainloop verbatim (128 thr, 2x2 warps, 3-stage) ----
__global__ void __launch_bounds__(128, 2) givens_main(
    const float* __restrict__ h_prev, const float* __restrict__ b_angle,
    const float* __restrict__ b_decay, const float* __restrict__ b_in,
    float* __restrict__ out)
{
    extern __shared__ __align__(1024) char smem[];
    const uint32_t sb = smem_u32(smem);
    const int tid = threadIdx.x, warp = tid >> 5, lane = tid & 31;
    const int g = lane >> 2, tg = lane & 3;
    const int wm = warp >> 1, wn = warp & 1;            // 2x2 warp grid
    const int by = blockIdx.y, cb = blockIdx.x;
    const int m0 = by * MT, n0 = cb * NT, a0 = n0 >> 1;

    // per-thread cp.async source bases (bytes)
    const char* xA = (const char*)g_xA;
    const char* WB = (const char*)g_WB;
    const size_t axbase = (size_t)by * 1048576 + (size_t)warp * 512 + lane * 16;
    const size_t wbbase = (size_t)cb * 851968 + (size_t)(tid >> 6) * 65536
                        + ((tid >> 4) & 3) * 256 + (tid & 15) * 16;
    const bool btail = (tid < 64);

    float ci[4][4][4] = {};   // mi, nb, frag
    float ca[4][2][4] = {};   // mi, na, frag
    float cd[4][4]    = {};   // mi, frag (wn==0 only)

    #define ISSUE(CHUNK, STG) do {                                              \
        uint32_t sd = sb + (STG) * STAGE_BYTES;                                 \
        const char* xs = xA + axbase + (size_t)(CHUNK) * 2048;                  \
        const char* ws = WB + wbbase + (size_t)(CHUNK) * 1024;                  \
        _Pragma("unroll")                                                       \
        for (int it = 0; it < 8; it++)                                          \
            cp16(sd + tid * 16 + it * 2048, xs + (size_t)it * 131072);          \
        _Pragma("unroll")                                                       \
        for (int ib = 0; ib < 7; ib++)                                          \
            if (ib < 6 || btail)                                                \
                cp16(sd + 16384 + ib * 2048 + tid * 16, ws + (size_t)ib * 131072); \
        asm volatile("cp.async.commit_group;" ::: "memory");                    \
    } while (0)

    ISSUE(0, 0);
    ISSUE(1, 1);

    #pragma unroll 1
    for (int c = 0; c < 64; c++) {
        asm volatile("cp.async.wait_group 1;" ::: "memory");
        __syncthreads();
        if (c + 2 < 64) { ISSUE(c + 2, (c + 2) % 3); }
        else            { asm volatile("cp.async.commit_group;" ::: "memory"); }

        const uint32_t sa = sb + (c % 3) * STAGE_BYTES;
        #pragma unroll
        for (int kt = 0; kt < 4; kt++) {
            uint32_t a[4][4];
            #pragma unroll
            for (int mi = 0; mi < 4; mi++)
                lds128(a[mi], sa + (uint32_t)(((wm * 4 + mi) * 4 + kt) * 512) + lane * 16);
            #pragma unroll
            for (int nb = 0; nb < 4; nb++) {
                uint32_t b[2];
                lds64(b, sa + A_STAGE + (uint32_t)(((wn * 4 + nb) * 4 + kt) * 256) + lane * 8);
                #pragma unroll
                for (int mi = 0; mi < 4; mi++) mma_tf32(ci[mi][nb], a[mi], b);
            }
            #pragma unroll
            for (int na = 0; na < 2; na++) {
                uint32_t b[2];
                lds64(b, sa + A_STAGE + (uint32_t)(((8 + wn * 2 + na) * 4 + kt) * 256) + lane * 8);
                #pragma unroll
                for (int mi = 0; mi < 4; mi++) mma_tf32(ca[mi][na], a[mi], b);
            }
            if (wn == 0) {
                uint32_t b[2];
                lds64(b, sa + A_STAGE + (uint32_t)((12 * 4 + kt) * 256) + lane * 8);
                #pragma unroll
                for (int mi = 0; mi < 4; mi++) mma_tf32(cd[mi], a[mi], b);
            }
        }
    }
    __syncthreads();

    // ---- epilogue ----
    float* ang_sm = (float*)smem;                       // 128 x 33 (stage0 reuse)
    float* dec_sm = (float*)(smem + SM_DEC);            // 128 floats
    const float bdec = b_decay[0];
    if (wn == 0 && tg == 0) {
        #pragma unroll
        for (int mi = 0; mi < 4; mi++) {
            int r = wm * 64 + mi * 16 + g;
            dec_sm[r]     = 1.f / (1.f + __expf(-(cd[mi][0] + bdec)));
            dec_sm[r + 8] = 1.f / (1.f + __expf(-(cd[mi][2] + bdec)));
        }
    }
    #pragma unroll
    for (int mi = 0; mi < 4; mi++)
    #pragma unroll
    for (int na = 0; na < 2; na++) {
        int rm  = wm * 64 + mi * 16 + g;
        int cbp = wn * 16 + na * 8 + 2 * tg;
        float bA0 = b_angle[a0 + cbp], bA1 = b_angle[a0 + cbp + 1];
        ang_sm[ rm      * 33 + cbp    ] = ca[mi][na][0] + bA0;
        ang_sm[ rm      * 33 + cbp + 1] = ca[mi][na][1] + bA1;
        ang_sm[(rm + 8) * 33 + cbp    ] = ca[mi][na][2] + bA0;
        ang_sm[(rm + 8) * 33 + cbp + 1] = ca[mi][na][3] + bA1;
    }
    __syncthreads();

    #pragma unroll
    for (int mi = 0; mi < 4; mi++)
    #pragma unroll
    for (int nb = 0; nb < 4; nb++) {
        int cloc = wn * 32 + nb * 8 + 2 * tg;
        float2 bi2 = *(const float2*)&b_in[n0 + cloc];
        #pragma unroll
        for (int h = 0; h < 2; h++) {
            int rloc = wm * 64 + mi * 16 + g + h * 8;
            size_t goff = (size_t)(m0 + rloc) * D_MODEL + n0 + cloc;
            float theta = ang_sm[rloc * 33 + (cloc >> 1)];
            float sn, cs;
            __sincosf(theta, &sn, &cs);
            float2 hp = *(const float2*)&h_prev[goff];
            float d = dec_sm[rloc];
            float2 o;
            o.x = d * (cs * hp.x - sn * hp.y) + ci[mi][nb][h * 2 + 0] + bi2.x;
            o.y = d * (sn * hp.x + cs * hp.y) + ci[mi][nb][h * 2 + 1] + bi2.y;
            *(float2*)&out[goff] = o;
        }
    }
    #undef ISSUE
}

extern "C" void kernel_launch(void* const* d_in, const int* in_sizes, int n_in,
                              void* d_out, int out_size) {
    const float* x       = (const float*)d_in[0];
    const float* h_prev  = (const float*)d_in[1];
    const float* W_angle = (const float*)d_in[2];
    const float* b_angle = (const float*)d_in[3];
    const float* W_decay = (const float*)d_in[4];
    const float* b_decay = (const float*)d_in[5];
    const float* W_in    = (const float*)d_in[6];
    const float* b_in    = (const float*)d_in[7];

    preround_x<<<4096, 256>>>(x);
    preround_w<<<26624, 256>>>(W_in, W_angle, W_decay);

    cudaFuncSetAttribute(givens_main, cudaFuncAttributeMaxDynamicSharedMemorySize, SMEM_TOTAL);
    dim3 grid(D_MODEL / NT, BATCH / MT);
    givens_main<<<grid, 128, SMEM_TOTAL>>>(h_prev, b_angle, b_decay, b_in, (float*)d_out);
}

// round 9
// speedup vs baseline: 1.6054x; 1.1379x over previous
#include <cuda_runtime.h>
#include <cstdint>

#define D_MODEL 2048
#define BATCH   16384
#define MT 128
#define NT 64
#define A_STAGE 16384
#define STAGE_BYTES 28672        // A 16KB + B 12KB
#define SMEM_TOTAL (3*STAGE_BYTES + 512)

// scratch: x in A-fragment order, weights in B-fragment order, decay vector
__device__ float g_xA[33554432];   // [rt 0..1023][t 0..255][128 w]
__device__ float g_WB[6291456];    // [cb 0..31][bt 0..11][t 0..255][64 w]
__device__ float g_dec[16384];     // sigmoid(x @ W_decay + b_decay)

__device__ __forceinline__ float tf32r(float x) {
    float y; asm("cvt.rna.tf32.f32 %0, %1;" : "=f"(y) : "f"(x)); return y;
}
__device__ __forceinline__ uint32_t smem_u32(const void* p) {
    uint32_t a;
    asm("{ .reg .u64 t; cvta.to.shared.u64 t, %1; cvt.u32.u64 %0, t; }" : "=r"(a) : "l"(p));
    return a;
}
__device__ __forceinline__ void cp16(uint32_t dst, const void* src) {
    asm volatile("cp.async.cg.shared.global [%0], [%1], 16;" :: "r"(dst), "l"(src));
}
__device__ __forceinline__ void lds128(uint32_t* r, uint32_t a) {
    asm volatile("ld.shared.v4.b32 {%0,%1,%2,%3}, [%4];"
                 : "=r"(r[0]), "=r"(r[1]), "=r"(r[2]), "=r"(r[3]) : "r"(a));
}
__device__ __forceinline__ void lds64(uint32_t* r, uint32_t a) {
    asm volatile("ld.shared.v2.b32 {%0,%1}, [%2];" : "=r"(r[0]), "=r"(r[1]) : "r"(a));
}
__device__ __forceinline__ void mma_tf32(float* c, const uint32_t* a, const uint32_t* b) {
    asm volatile(
        "mma.sync.aligned.m16n8k8.row.col.f32.tf32.tf32.f32 "
        "{%0,%1,%2,%3}, {%4,%5,%6,%7}, {%8,%9}, {%0,%1,%2,%3};\n"
        : "+f"(c[0]), "+f"(c[1]), "+f"(c[2]), "+f"(c[3])
        : "r"(a[0]), "r"(a[1]), "r"(a[2]), "r"(a[3]), "r"(b[0]), "r"(b[1]));
}

// ---- decay GEMV: one warp per row, fp32 exact ----
__global__ __launch_bounds__(256) void decay_gemv(const float* __restrict__ x,
                                                  const float* __restrict__ Wd,
                                                  const float* __restrict__ bd) {
    const int warp = threadIdx.x >> 5, lane = threadIdx.x & 31;
    const int row = blockIdx.x * 8 + warp;
    const float4* xr = (const float4*)(x + (size_t)row * D_MODEL);
    const float4* wd = (const float4*)Wd;
    float s = 0.f;
    #pragma unroll
    for (int i = 0; i < 16; i++) {
        int idx = lane + i * 32;
        float4 a = xr[idx], b = wd[idx];
        s += a.x * b.x + a.y * b.y + a.z * b.z + a.w * b.w;
    }
    #pragma unroll
    for (int o = 16; o > 0; o >>= 1) s += __shfl_xor_sync(0xFFFFFFFFu, s, o);
    if (lane == 0) g_dec[row] = 1.f / (1.f + __expf(-(s + bd[0])));
}

// ---- preround x: coalesced LDG -> smem permute -> coalesced STG (42us) ----
__global__ __launch_bounds__(256) void preround_x(const float* __restrict__ x) {
    __shared__ float sm[16 * 516];
    const int tid = threadIdx.x;
    const int rt = blockIdx.x >> 2, tb = blockIdx.x & 3;
    const float* src = x + (size_t)rt * 16 * D_MODEL + tb * 512;
    #pragma unroll
    for (int i = 0; i < 8; i++) {
        int f4 = tid + i * 256;
        int row = f4 >> 7, c4 = f4 & 127;
        float4 v = *(const float4*)(src + (size_t)row * D_MODEL + c4 * 4);
        v.x = tf32r(v.x); v.y = tf32r(v.y); v.z = tf32r(v.z); v.w = tf32r(v.w);
        *(float4*)&sm[row * 516 + c4 * 4] = v;
    }
    __syncthreads();
    char* dst = (char*)g_xA + (size_t)rt * 131072 + (size_t)tb * 64 * 512;
    #pragma unroll
    for (int i = 0; i < 8; i++) {
        int f4 = tid + i * 256;
        int tl = f4 >> 5, lane = f4 & 31;
        int g = lane >> 2, tg = lane & 3;
        float4 v;
        v.x = sm[ g      * 516 + tl * 8 + tg    ];
        v.y = sm[(g + 8) * 516 + tl * 8 + tg    ];
        v.z = sm[ g      * 516 + tl * 8 + tg + 4];
        v.w = sm[(g + 8) * 516 + tl * 8 + tg + 4];
        *(float4*)(dst + (size_t)tl * 512 + lane * 16) = v;
    }
}

// ---- preround W: W_in/W_angle -> concatenated B-fragment order (12 bt) ----
__global__ void preround_w(const float* __restrict__ Wi, const float* __restrict__ Wa) {
    size_t f = (size_t)blockIdx.x * 256 + threadIdx.x;      // 6291456 total
    int cb = (int)(f / 196608); int rem = (int)(f % 196608);
    int bt = rem >> 14; int rem2 = rem & 16383;
    int t = rem2 >> 6; int w = rem2 & 63;
    int lane = w >> 1, j = w & 1, g = lane >> 2, tg = lane & 3;
    int k = t * 8 + tg + 4 * j;
    float v;
    if (bt < 8) v = Wi[(size_t)(cb * 64 + bt * 8 + g) * D_MODEL + k];
    else        v = Wa[(size_t)(cb * 32 + (bt - 8) * 8 + g) * D_MODEL + k];
    g_WB[f] = tf32r(v);
}

// ---- main fused kernel: 128 thr, 2x2 warps, 3-stage, uniform 96-col MMA ----
__global__ void __launch_bounds__(128, 2) givens_main(
    const float* __restrict__ h_prev, const float* __restrict__ b_angle,
    const float* __restrict__ b_in, float* __restrict__ out)
{
    extern __shared__ __align__(1024) char smem[];
    const uint32_t sb = smem_u32(smem);
    const int tid = threadIdx.x, warp = tid >> 5, lane = tid & 31;
    const int g = lane >> 2, tg = lane & 3;
    const int wm = warp >> 1, wn = warp & 1;            // 2x2 warp grid
    const int by = blockIdx.y, cb = blockIdx.x;
    const int m0 = by * MT, n0 = cb * NT, a0 = n0 >> 1;

    // per-thread cp.async source bases (bytes)
    const char* xA = (const char*)g_xA;
    const char* WB = (const char*)g_WB;
    const size_t axbase = (size_t)by * 1048576 + (size_t)warp * 512 + lane * 16;
    const size_t wbbase = (size_t)cb * 786432 + (size_t)(tid >> 6) * 65536
                        + ((tid >> 4) & 3) * 256 + (tid & 15) * 16;

    float ci[4][4][4] = {};   // mi, nb, frag
    float ca[4][2][4] = {};   // mi, na, frag

    #define ISSUE(CHUNK, STG) do {                                              \
        uint32_t sd = sb + (STG) * STAGE_BYTES;                                 \
        const char* xs = xA + axbase + (size_t)(CHUNK) * 2048;                  \
        const char* ws = WB + wbbase + (size_t)(CHUNK) * 1024;                  \
        _Pragma("unroll")                                                       \
        for (int it = 0; it < 8; it++)                                          \
            cp16(sd + tid * 16 + it * 2048, xs + (size_t)it * 131072);          \
        _Pragma("unroll")                                                       \
        for (int ib = 0; ib < 6; ib++)                                          \
            cp16(sd + 16384 + ib * 2048 + tid * 16, ws + (size_t)ib * 131072);  \
        asm volatile("cp.async.commit_group;" ::: "memory");                    \
    } while (0)

    ISSUE(0, 0);
    ISSUE(1, 1);

    #pragma unroll 1
    for (int c = 0; c < 64; c++) {
        asm volatile("cp.async.wait_group 1;" ::: "memory");
        __syncthreads();
        if (c + 2 < 64) { ISSUE(c + 2, (c + 2) % 3); }
        else            { asm volatile("cp.async.commit_group;" ::: "memory"); }

        const uint32_t sa = sb + (c % 3) * STAGE_BYTES;
        #pragma unroll
        for (int kt = 0; kt < 4; kt++) {
            uint32_t a[4][4];
            #pragma unroll
            for (int mi = 0; mi < 4; mi++)
                lds128(a[mi], sa + (uint32_t)(((wm * 4 + mi) * 4 + kt) * 512) + lane * 16);
            #pragma unroll
            for (int nb = 0; nb < 4; nb++) {
                uint32_t b[2];
                lds64(b, sa + A_STAGE + (uint32_t)(((wn * 4 + nb) * 4 + kt) * 256) + lane * 8);
                #pragma unroll
                for (int mi = 0; mi < 4; mi++) mma_tf32(ci[mi][nb], a[mi], b);
            }
            #pragma unroll
            for (int na = 0; na < 2; na++) {
                uint32_t b[2];
                lds64(b, sa + A_STAGE + (uint32_t)(((8 + wn * 2 + na) * 4 + kt) * 256) + lane * 8);
                #pragma unroll
                for (int mi = 0; mi < 4; mi++) mma_tf32(ca[mi][na], a[mi], b);
            }
        }
    }
    __syncthreads();

    // ---- epilogue ----
    float* ang_sm = (float*)smem;                       // 128 x 33 (stage0 reuse)
    #pragma unroll
    for (int mi = 0; mi < 4; mi++)
    #pragma unroll
    for (int na = 0; na < 2; na++) {
        int rm  = wm * 64 + mi * 16 + g;
        int cbp = wn * 16 + na * 8 + 2 * tg;
        float bA0 = b_angle[a0 + cbp], bA1 = b_angle[a0 + cbp + 1];
        ang_sm[ rm      * 33 + cbp    ] = ca[mi][na][0] + bA0;
        ang_sm[ rm      * 33 + cbp + 1] = ca[mi][na][1] + bA1;
        ang_sm[(rm + 8) * 33 + cbp    ] = ca[mi][na][2] + bA0;
        ang_sm[(rm + 8) * 33 + cbp + 1] = ca[mi][na][3] + bA1;
    }
    // decay per owned row (8 rows/thread), loaded once into registers
    float drow[4][2];
    #pragma unroll
    for (int mi = 0; mi < 4; mi++)
    #pragma unroll
    for (int h = 0; h < 2; h++)
        drow[mi][h] = g_dec[m0 + wm * 64 + mi * 16 + g + h * 8];
    __syncthreads();

    #pragma unroll
    for (int mi = 0; mi < 4; mi++)
    #pragma unroll
    for (int nb = 0; nb < 4; nb++) {
        int cloc = wn * 32 + nb * 8 + 2 * tg;
        float2 bi2 = *(const float2*)&b_in[n0 + cloc];
        #pragma unroll
        for (int h = 0; h < 2; h++) {
            int rloc = wm * 64 + mi * 16 + g + h * 8;
            size_t goff = (size_t)(m0 + rloc) * D_MODEL + n0 + cloc;
            float theta = ang_sm[rloc * 33 + (cloc >> 1)];
            float sn, cs;
            __sincosf(theta, &sn, &cs);
            float2 hp = *(const float2*)&h_prev[goff];
            float d = drow[mi][h];
            float2 o;
            o.x = d * (cs * hp.x - sn * hp.y) + ci[mi][nb][h * 2 + 0] + bi2.x;
            o.y = d * (sn * hp.x + cs * hp.y) + ci[mi][nb][h * 2 + 1] + bi2.y;
            *(float2*)&out[goff] = o;
        }
    }
    #undef ISSUE
}

extern "C" void kernel_launch(void* const* d_in, const int* in_sizes, int n_in,
                              void* d_out, int out_size) {
    const float* x       = (const float*)d_in[0];
    const float* h_prev  = (const float*)d_in[1];
    const float* W_angle = (const float*)d_in[2];
    const float* b_angle = (const float*)d_in[3];
    const float* W_decay = (const float*)d_in[4];
    const float* b_decay = (const float*)d_in[5];
    const float* W_in    = (const float*)d_in[6];
    const float* b_in    = (const float*)d_in[7];

    preround_x<<<4096, 256>>>(x);
    decay_gemv<<<2048, 256>>>(x, W_decay, b_decay);
    preround_w<<<24576, 256>>>(W_in, W_angle);

    cudaFuncSetAttribute(givens_main, cudaFuncAttributeMaxDynamicSharedMemorySize, SMEM_TOTAL);
    dim3 grid(D_MODEL / NT, BATCH / MT);
    givens_main<<<grid, 128, SMEM_TOTAL>>>(h_prev, b_angle, b_in, (float*)d_out);
}

// round 10
// speedup vs baseline: 1.7273x; 1.0759x over previous
#include <cuda_runtime.h>
#include <cstdint>

#define D_MODEL 2048
#define BATCH   16384
#define MT 128
#define NT 64
#define A_STAGE 16384
#define STAGE_BYTES 28672        // A 16KB + B 12KB
#define SMEM_TOTAL (4*STAGE_BYTES + 512)   // 115200/CTA, 2 CTA = 230400 <= 233472

// scratch: x in A-fragment order, weights in B-fragment order, decay vector
__device__ float g_xA[33554432];   // [rt 0..1023][t 0..255][128 w]
__device__ float g_WB[6291456];    // [cb 0..31][bt 0..11][t 0..255][64 w]
__device__ float g_dec[16384];     // sigmoid(x @ W_decay + b_decay)

__device__ __forceinline__ float tf32r(float x) {
    float y; asm("cvt.rna.tf32.f32 %0, %1;" : "=f"(y) : "f"(x)); return y;
}
__device__ __forceinline__ uint32_t smem_u32(const void* p) {
    uint32_t a;
    asm("{ .reg .u64 t; cvta.to.shared.u64 t, %1; cvt.u32.u64 %0, t; }" : "=r"(a) : "l"(p));
    return a;
}
__device__ __forceinline__ void cp16(uint32_t dst, const void* src) {
    asm volatile("cp.async.cg.shared.global [%0], [%1], 16;" :: "r"(dst), "l"(src));
}
__device__ __forceinline__ void lds128(uint32_t* r, uint32_t a) {
    asm volatile("ld.shared.v4.b32 {%0,%1,%2,%3}, [%4];"
                 : "=r"(r[0]), "=r"(r[1]), "=r"(r[2]), "=r"(r[3]) : "r"(a));
}
__device__ __forceinline__ void lds64(uint32_t* r, uint32_t a) {
    asm volatile("ld.shared.v2.b32 {%0,%1}, [%2];" : "=r"(r[0]), "=r"(r[1]) : "r"(a));
}
__device__ __forceinline__ void mma_tf32(float* c, const uint32_t* a, const uint32_t* b) {
    asm volatile(
        "mma.sync.aligned.m16n8k8.row.col.f32.tf32.tf32.f32 "
        "{%0,%1,%2,%3}, {%4,%5,%6,%7}, {%8,%9}, {%0,%1,%2,%3};\n"
        : "+f"(c[0]), "+f"(c[1]), "+f"(c[2]), "+f"(c[3])
        : "r"(a[0]), "r"(a[1]), "r"(a[2]), "r"(a[3]), "r"(b[0]), "r"(b[1]));
}

// ---- decay GEMV: one warp per row, fp32 exact ----
__global__ __launch_bounds__(256) void decay_gemv(const float* __restrict__ x,
                                                  const float* __restrict__ Wd,
                                                  const float* __restrict__ bd) {
    const int warp = threadIdx.x >> 5, lane = threadIdx.x & 31;
    const int row = blockIdx.x * 8 + warp;
    const float4* xr = (const float4*)(x + (size_t)row * D_MODEL);
    const float4* wd = (const float4*)Wd;
    float s = 0.f;
    #pragma unroll
    for (int i = 0; i < 16; i++) {
        int idx = lane + i * 32;
        float4 a = xr[idx], b = wd[idx];
        s += a.x * b.x + a.y * b.y + a.z * b.z + a.w * b.w;
    }
    #pragma unroll
    for (int o = 16; o > 0; o >>= 1) s += __shfl_xor_sync(0xFFFFFFFFu, s, o);
    if (lane == 0) g_dec[row] = 1.f / (1.f + __expf(-(s + bd[0])));
}

// ---- preround x: coalesced LDG -> smem permute -> coalesced STG (42us) ----
__global__ __launch_bounds__(256) void preround_x(const float* __restrict__ x) {
    __shared__ float sm[16 * 516];
    const int tid = threadIdx.x;
    const int rt = blockIdx.x >> 2, tb = blockIdx.x & 3;
    const float* src = x + (size_t)rt * 16 * D_MODEL + tb * 512;
    #pragma unroll
    for (int i = 0; i < 8; i++) {
        int f4 = tid + i * 256;
        int row = f4 >> 7, c4 = f4 & 127;
        float4 v = *(const float4*)(src + (size_t)row * D_MODEL + c4 * 4);
        v.x = tf32r(v.x); v.y = tf32r(v.y); v.z = tf32r(v.z); v.w = tf32r(v.w);
        *(float4*)&sm[row * 516 + c4 * 4] = v;
    }
    __syncthreads();
    char* dst = (char*)g_xA + (size_t)rt * 131072 + (size_t)tb * 64 * 512;
    #pragma unroll
    for (int i = 0; i < 8; i++) {
        int f4 = tid + i * 256;
        int tl = f4 >> 5, lane = f4 & 31;
        int g = lane >> 2, tg = lane & 3;
        float4 v;
        v.x = sm[ g      * 516 + tl * 8 + tg    ];
        v.y = sm[(g + 8) * 516 + tl * 8 + tg    ];
        v.z = sm[ g      * 516 + tl * 8 + tg + 4];
        v.w = sm[(g + 8) * 516 + tl * 8 + tg + 4];
        *(float4*)(dst + (size_t)tl * 512 + lane * 16) = v;
    }
}

// ---- preround W: W_in/W_angle -> concatenated B-fragment order (12 bt) ----
__global__ void preround_w(const float* __restrict__ Wi, const float* __restrict__ Wa) {
    size_t f = (size_t)blockIdx.x * 256 + threadIdx.x;      // 6291456 total
    int cb = (int)(f / 196608); int rem = (int)(f % 196608);
    int bt = rem >> 14; int rem2 = rem & 16383;
    int t = rem2 >> 6; int w = rem2 & 63;
    int lane = w >> 1, j = w & 1, g = lane >> 2, tg = lane & 3;
    int k = t * 8 + tg + 4 * j;
    float v;
    if (bt < 8) v = Wi[(size_t)(cb * 64 + bt * 8 + g) * D_MODEL + k];
    else        v = Wa[(size_t)(cb * 32 + (bt - 8) * 8 + g) * D_MODEL + k];
    g_WB[f] = tf32r(v);
}

// ---- main: 128 thr, 2x2 warps, 4 stages, one sync per 2 chunks ----
__global__ void __launch_bounds__(128, 2) givens_main(
    const float* __restrict__ h_prev, const float* __restrict__ b_angle,
    const float* __restrict__ b_in, float* __restrict__ out)
{
    extern __shared__ __align__(1024) char smem[];
    const uint32_t sb = smem_u32(smem);
    const int tid = threadIdx.x, warp = tid >> 5, lane = tid & 31;
    const int g = lane >> 2, tg = lane & 3;
    const int wm = warp >> 1, wn = warp & 1;            // 2x2 warp grid
    const int by = blockIdx.y, cb = blockIdx.x;
    const int m0 = by * MT, n0 = cb * NT, a0 = n0 >> 1;

    const char* xA = (const char*)g_xA;
    const char* WB = (const char*)g_WB;
    const size_t axbase = (size_t)by * 1048576 + (size_t)warp * 512 + lane * 16;
    const size_t wbbase = (size_t)cb * 786432 + (size_t)(tid >> 6) * 65536
                        + ((tid >> 4) & 3) * 256 + (tid & 15) * 16;

    float ci[4][4][4] = {};   // mi, nb, frag
    float ca[4][2][4] = {};   // mi, na, frag

    #define ISSUE(CHUNK) do {                                                   \
        uint32_t sd = sb + ((CHUNK) & 3) * STAGE_BYTES;                          \
        const char* xs = xA + axbase + (size_t)(CHUNK) * 2048;                   \
        const char* ws = WB + wbbase + (size_t)(CHUNK) * 1024;                   \
        _Pragma("unroll")                                                        \
        for (int it = 0; it < 8; it++)                                           \
            cp16(sd + tid * 16 + it * 2048, xs + (size_t)it * 131072);           \
        _Pragma("unroll")                                                        \
        for (int ib = 0; ib < 6; ib++)                                           \
            cp16(sd + 16384 + ib * 2048 + tid * 16, ws + (size_t)ib * 131072);   \
        asm volatile("cp.async.commit_group;" ::: "memory");                     \
    } while (0)

    #define COMPUTE(CHUNK) do {                                                  \
        const uint32_t sa = sb + ((CHUNK) & 3) * STAGE_BYTES;                     \
        _Pragma("unroll")                                                         \
        for (int kt = 0; kt < 4; kt++) {                                          \
            uint32_t a[4][4];                                                     \
            _Pragma("unroll")                                                     \
            for (int mi = 0; mi < 4; mi++)                                        \
                lds128(a[mi], sa + (uint32_t)(((wm * 4 + mi) * 4 + kt) * 512) + lane * 16); \
            _Pragma("unroll")                                                     \
            for (int nb = 0; nb < 4; nb++) {                                      \
                uint32_t b[2];                                                    \
                lds64(b, sa + A_STAGE + (uint32_t)(((wn * 4 + nb) * 4 + kt) * 256) + lane * 8); \
                _Pragma("unroll")                                                 \
                for (int mi = 0; mi < 4; mi++) mma_tf32(ci[mi][nb], a[mi], b);    \
            }                                                                     \
            _Pragma("unroll")                                                     \
            for (int na = 0; na < 2; na++) {                                      \
                uint32_t b[2];                                                    \
                lds64(b, sa + A_STAGE + (uint32_t)(((8 + wn * 2 + na) * 4 + kt) * 256) + lane * 8); \
                _Pragma("unroll")                                                 \
                for (int mi = 0; mi < 4; mi++) mma_tf32(ca[mi][na], a[mi], b);    \
            }                                                                     \
        }                                                                         \
    } while (0)

    ISSUE(0);
    ISSUE(1);

    #pragma unroll 1
    for (int cc = 0; cc < 32; cc++) {
        const int c0 = cc * 2;
        asm volatile("cp.async.wait_group 0;" ::: "memory");
        __syncthreads();
        if (c0 + 2 < 64) ISSUE(c0 + 2);           // overwrites stage of c0-2 (read done)
        COMPUTE(c0);
        if (c0 + 3 < 64) ISSUE(c0 + 3);           // overwrites stage of c0-1 (read done)
        COMPUTE(c0 + 1);
    }
    __syncthreads();

    // ---- epilogue ----
    float* ang_sm = (float*)smem;                       // 128 x 33 (stage0 reuse)
    #pragma unroll
    for (int mi = 0; mi < 4; mi++)
    #pragma unroll
    for (int na = 0; na < 2; na++) {
        int rm  = wm * 64 + mi * 16 + g;
        int cbp = wn * 16 + na * 8 + 2 * tg;
        float bA0 = b_angle[a0 + cbp], bA1 = b_angle[a0 + cbp + 1];
        ang_sm[ rm      * 33 + cbp    ] = ca[mi][na][0] + bA0;
        ang_sm[ rm      * 33 + cbp + 1] = ca[mi][na][1] + bA1;
        ang_sm[(rm + 8) * 33 + cbp    ] = ca[mi][na][2] + bA0;
        ang_sm[(rm + 8) * 33 + cbp + 1] = ca[mi][na][3] + bA1;
    }
    float drow[4][2];
    #pragma unroll
    for (int mi = 0; mi < 4; mi++)
    #pragma unroll
    for (int h = 0; h < 2; h++)
        drow[mi][h] = g_dec[m0 + wm * 64 + mi * 16 + g + h * 8];
    __syncthreads();

    #pragma unroll
    for (int mi = 0; mi < 4; mi++)
    #pragma unroll
    for (int nb = 0; nb < 4; nb++) {
        int cloc = wn * 32 + nb * 8 + 2 * tg;
        float2 bi2 = *(const float2*)&b_in[n0 + cloc];
        #pragma unroll
        for (int h = 0; h < 2; h++) {
            int rloc = wm * 64 + mi * 16 + g + h * 8;
            size_t goff = (size_t)(m0 + rloc) * D_MODEL + n0 + cloc;
            float theta = ang_sm[rloc * 33 + (cloc >> 1)];
            float sn, cs;
            __sincosf(theta, &sn, &cs);
            float2 hp = *(const float2*)&h_prev[goff];
            float d = drow[mi][h];
            float2 o;
            o.x = d * (cs * hp.x - sn * hp.y) + ci[mi][nb][h * 2 + 0] + bi2.x;
            o.y = d * (sn * hp.x + cs * hp.y) + ci[mi][nb][h * 2 + 1] + bi2.y;
            *(float2*)&out[goff] = o;
        }
    }
    #undef ISSUE
    #undef COMPUTE
}

extern "C" void kernel_launch(void* const* d_in, const int* in_sizes, int n_in,
                              void* d_out, int out_size) {
    const float* x       = (const float*)d_in[0];
    const float* h_prev  = (const float*)d_in[1];
    const float* W_angle = (const float*)d_in[2];
    const float* b_angle = (const float*)d_in[3];
    const float* W_decay = (const float*)d_in[4];
    const float* b_decay = (const float*)d_in[5];
    const float* W_in    = (const float*)d_in[6];
    const float* b_in    = (const float*)d_in[7];

    preround_x<<<4096, 256>>>(x);
    decay_gemv<<<2048, 256>>>(x, W_decay, b_decay);
    preround_w<<<24576, 256>>>(W_in, W_angle);

    cudaFuncSetAttribute(givens_main, cudaFuncAttributeMaxDynamicSharedMemorySize, SMEM_TOTAL);
    dim3 grid(D_MODEL / NT, BATCH / MT);
    givens_main<<<grid, 128, SMEM_TOTAL>>>(h_prev, b_angle, b_in, (float*)d_out);
}